// round 1
// baseline (speedup 1.0000x reference)
#include <cuda_runtime.h>
#include <cstdint>

// RBF kernel: out[i][j] = exp(-||x_i - y_j||^2), N=M=8192, D=64, fp32.
// Strategy: dist2 = xn[i] + yn[j] - 2*dot(x_i, y_j).
// dot computed by a register-blocked SGEMM using packed fma.rn.f32x2 with
// K-pair packing: acc holds {sum over even k, sum over odd k}; both MMA
// operands are natural adjacent-k float2 loads from SMEM (no dup MOVs).

#define NN 8192
#define DD 64
#define TILE_I 128
#define TILE_J 64
#define XS_STRIDE 66   // pad 64->66 floats: conflict-free strided float2 reads
#define YS_STRIDE 66
#define SMEM_FLOATS (TILE_I * XS_STRIDE + TILE_J * YS_STRIDE)
#define SMEM_BYTES (SMEM_FLOATS * 4)

__device__ float g_xn[NN];
__device__ float g_yn[NN];

// ---------------------------------------------------------------------------
// Row-norm precompute: one thread per row, handles x and y.
// ---------------------------------------------------------------------------
__global__ void norms_kernel(const float* __restrict__ x,
                             const float* __restrict__ y) {
    int i = blockIdx.x * blockDim.x + threadIdx.x;
    if (i >= NN) return;
    const float4* xr = reinterpret_cast<const float4*>(x + (size_t)i * DD);
    const float4* yr = reinterpret_cast<const float4*>(y + (size_t)i * DD);
    float sx = 0.f, sy = 0.f;
#pragma unroll
    for (int c = 0; c < DD / 4; c++) {
        float4 v = xr[c];
        sx = fmaf(v.x, v.x, sx); sx = fmaf(v.y, v.y, sx);
        sx = fmaf(v.z, v.z, sx); sx = fmaf(v.w, v.w, sx);
        float4 w = yr[c];
        sy = fmaf(w.x, w.x, sy); sy = fmaf(w.y, w.y, sy);
        sy = fmaf(w.z, w.z, sy); sy = fmaf(w.w, w.w, sy);
    }
    g_xn[i] = sx;
    g_yn[i] = sy;
}

// ---------------------------------------------------------------------------
// Main fused GEMM + exp kernel.
// Grid: (NN/TILE_J, NN/TILE_I) = (128, 64). Block: 256 threads (16x16).
// Each thread: 8 rows (ty + 16*ii) x 4 cols (tx + 16*jj).
// ---------------------------------------------------------------------------
__global__ __launch_bounds__(256, 2)
void rbf_main_kernel(const float* __restrict__ x,
                     const float* __restrict__ y,
                     float* __restrict__ out) {
    extern __shared__ float smem[];
    float* xs = smem;                        // [TILE_I][XS_STRIDE]
    float* ys = smem + TILE_I * XS_STRIDE;   // [TILE_J][YS_STRIDE]

    const int tid = threadIdx.x;
    const int tx = tid & 15;
    const int ty = tid >> 4;
    const int row0 = blockIdx.y * TILE_I;
    const int col0 = blockIdx.x * TILE_J;

    // ---- Load tiles: coalesced float2 gmem reads, one row per warp ----
    {
        const int r = tid >> 5;   // 0..7
        const int c = tid & 31;   // float2 column 0..31
#pragma unroll
        for (int it = 0; it < TILE_I / 8; it++) {
            int rr = r + it * 8;
            float2 v = reinterpret_cast<const float2*>(
                x + (size_t)(row0 + rr) * DD)[c];
            *reinterpret_cast<float2*>(&xs[rr * XS_STRIDE + 2 * c]) = v;
        }
#pragma unroll
        for (int it = 0; it < TILE_J / 8; it++) {
            int rr = r + it * 8;
            float2 v = reinterpret_cast<const float2*>(
                y + (size_t)(col0 + rr) * DD)[c];
            *reinterpret_cast<float2*>(&ys[rr * YS_STRIDE + 2 * c]) = v;
        }
    }
    __syncthreads();

    // ---- Mainloop: K-pair packed f32x2 FMAs ----
    unsigned long long acc[8][4];
#pragma unroll
    for (int ii = 0; ii < 8; ii++)
#pragma unroll
        for (int jj = 0; jj < 4; jj++)
            acc[ii][jj] = 0ull;  // {0.0f, 0.0f}

#pragma unroll 4
    for (int kp = 0; kp < DD / 2; kp++) {
        unsigned long long xv[8], yv[4];
#pragma unroll
        for (int ii = 0; ii < 8; ii++)
            xv[ii] = *reinterpret_cast<const unsigned long long*>(
                &xs[(ty + 16 * ii) * XS_STRIDE + 2 * kp]);
#pragma unroll
        for (int jj = 0; jj < 4; jj++)
            yv[jj] = *reinterpret_cast<const unsigned long long*>(
                &ys[(tx + 16 * jj) * YS_STRIDE + 2 * kp]);
#pragma unroll
        for (int ii = 0; ii < 8; ii++)
#pragma unroll
            for (int jj = 0; jj < 4; jj++)
                asm("fma.rn.f32x2 %0, %1, %2, %0;"
                    : "+l"(acc[ii][jj])
                    : "l"(xv[ii]), "l"(yv[jj]));
    }

    // ---- Epilogue: dist2 = xn + yn - 2*dot, out = exp(-dist2) ----
    float xn[8], yn[4];
#pragma unroll
    for (int ii = 0; ii < 8; ii++)
        xn[ii] = __ldg(&g_xn[row0 + ty + 16 * ii]);
#pragma unroll
    for (int jj = 0; jj < 4; jj++)
        yn[jj] = __ldg(&g_yn[col0 + tx + 16 * jj]);

#pragma unroll
    for (int ii = 0; ii < 8; ii++) {
        const size_t orow = (size_t)(row0 + ty + 16 * ii) * NN + col0;
#pragma unroll
        for (int jj = 0; jj < 4; jj++) {
            unsigned long long a = acc[ii][jj];
            float lo = __uint_as_float((unsigned)(a & 0xffffffffull));
            float hi = __uint_as_float((unsigned)(a >> 32));
            float dot = lo + hi;
            // neg_d2 = min(2*dot - (xn+yn), 0)  ==  -max(dist2, 0)
            float neg_d2 = fminf(fmaf(2.0f, dot, -(xn[ii] + yn[jj])), 0.0f);
            float e = __expf(neg_d2);
            __stcs(&out[orow + tx + 16 * jj], e);  // streaming: don't pollute L2
        }
    }
}

// ---------------------------------------------------------------------------
extern "C" void kernel_launch(void* const* d_in, const int* in_sizes, int n_in,
                              void* d_out, int out_size) {
    const float* x = (const float*)d_in[0];
    const float* y = (const float*)d_in[1];
    float* out = (float*)d_out;

    (void)in_sizes; (void)n_in; (void)out_size;

    // Opt in to >48KB dynamic smem (idempotent; safe under graph capture).
    cudaFuncSetAttribute(rbf_main_kernel,
                         cudaFuncAttributeMaxDynamicSharedMemorySize,
                         SMEM_BYTES);

    norms_kernel<<<NN / 256, 256>>>(x, y);
    dim3 grid(NN / TILE_J, NN / TILE_I);  // (128, 64)
    rbf_main_kernel<<<grid, 256, SMEM_BYTES>>>(x, y, out);
}

// round 4
// speedup vs baseline: 1.8647x; 1.8647x over previous
#include <cuda_runtime.h>
#include <cuda_bf16.h>
#include <cstdint>

// RBF: out[i][j] = exp(-||x_i - y_j||^2), N=M=8192, D=64, fp32.
// dist2 = xn + yn - 2*dot. dot via bf16 hi/lo split on mma.sync (HMMA):
//   x = xh + xl (bf16 each); dot = xh.yh + xh.yl + xl.yh (xl.yl dropped).
// CTA = 128x128 tile, K=64 smem-resident in 4 bf16 arrays (Ah,Al,Bh,Bl).

#define NN 8192
#define DD 64
#define TILE 128

// smem byte offsets (dynamic, 1024-aligned): 4 arrays of 128 rows x 128B
#define AH_OFF 0
#define AL_OFF 16384
#define BH_OFF 32768
#define BL_OFF 49152
#define SMEM_DYN_BYTES 65536

__device__ float g_xn[NN];
__device__ float g_yn[NN];

// ---------------------------------------------------------------------------
__global__ void norms_kernel(const float* __restrict__ x,
                             const float* __restrict__ y) {
    int i = blockIdx.x * blockDim.x + threadIdx.x;
    if (i >= NN) return;
    const float4* xr = reinterpret_cast<const float4*>(x + (size_t)i * DD);
    const float4* yr = reinterpret_cast<const float4*>(y + (size_t)i * DD);
    float sx = 0.f, sy = 0.f;
#pragma unroll
    for (int c = 0; c < DD / 4; c++) {
        float4 v = xr[c];
        sx = fmaf(v.x, v.x, sx); sx = fmaf(v.y, v.y, sx);
        sx = fmaf(v.z, v.z, sx); sx = fmaf(v.w, v.w, sx);
        float4 w = yr[c];
        sy = fmaf(w.x, w.x, sy); sy = fmaf(w.y, w.y, sy);
        sy = fmaf(w.z, w.z, sy); sy = fmaf(w.w, w.w, sy);
    }
    g_xn[i] = sx;
    g_yn[i] = sy;
}

// ------------------------- helpers -----------------------------------------
__device__ __forceinline__ uint32_t smem_u32(const void* p) {
    uint32_t a;
    asm("{ .reg .u64 t; cvta.to.shared.u64 t, %1; cvt.u32.u64 %0, t; }"
        : "=r"(a) : "l"(p));
    return a;
}

__device__ __forceinline__ void sts_v2(uint32_t addr, uint32_t a, uint32_t b) {
    asm volatile("st.shared.v2.b32 [%0], {%1, %2};"
                 :: "r"(addr), "r"(a), "r"(b) : "memory");
}

__device__ __forceinline__ void ldsm4(uint32_t addr, uint32_t& r0, uint32_t& r1,
                                      uint32_t& r2, uint32_t& r3) {
    asm volatile("ldmatrix.sync.aligned.m8n8.x4.shared.b16 {%0,%1,%2,%3}, [%4];"
                 : "=r"(r0), "=r"(r1), "=r"(r2), "=r"(r3) : "r"(addr));
}

__device__ __forceinline__ void mma16816(float& c0, float& c1, float& c2, float& c3,
                                         uint32_t a0, uint32_t a1, uint32_t a2,
                                         uint32_t a3, uint32_t b0, uint32_t b1) {
    asm volatile(
        "mma.sync.aligned.m16n8k16.row.col.f32.bf16.bf16.f32 "
        "{%0,%1,%2,%3}, {%4,%5,%6,%7}, {%8,%9}, {%0,%1,%2,%3};"
        : "+f"(c0), "+f"(c1), "+f"(c2), "+f"(c3)
        : "r"(a0), "r"(a1), "r"(a2), "r"(a3), "r"(b0), "r"(b1));
}

// swizzled address: row stride 128B, 16B chunk index XORed with row&7
__device__ __forceinline__ uint32_t swz(uint32_t base, int row, int chunk) {
    return base + row * 128 + (((unsigned)chunk ^ ((unsigned)row & 7u)) << 4);
}

// fp32 -> {hi,lo} bf16x2 packed pair for 2 consecutive values
__device__ __forceinline__ void split2(float v0, float v1,
                                       uint32_t& hp, uint32_t& lp) {
    __nv_bfloat16 h0 = __float2bfloat16(v0);
    __nv_bfloat16 h1 = __float2bfloat16(v1);
    __nv_bfloat16 l0 = __float2bfloat16(v0 - __bfloat162float(h0));
    __nv_bfloat16 l1 = __float2bfloat16(v1 - __bfloat162float(h1));
    __nv_bfloat162 hh(h0, h1), ll(l0, l1);
    hp = *reinterpret_cast<uint32_t*>(&hh);
    lp = *reinterpret_cast<uint32_t*>(&ll);
}

// ---------------------------------------------------------------------------
// Main kernel. 256 threads (8 warps: 2 row x 4 col), grid (64, 64).
// ---------------------------------------------------------------------------
__global__ __launch_bounds__(256, 2)
void rbf_mma_kernel(const float* __restrict__ x,
                    const float* __restrict__ y,
                    float* __restrict__ out) {
    extern __shared__ __align__(128) char smem_raw[];
    const uint32_t sbase = smem_u32(smem_raw);

    __shared__ float xn_s[TILE];
    __shared__ float yn_s[TILE];

    const int t    = threadIdx.x;
    const int wid  = t >> 5;
    const int lane = t & 31;
    const int row0 = blockIdx.y * TILE;
    const int col0 = blockIdx.x * TILE;

    // ---- Load + split x tile -> Ah/Al ----
#pragma unroll
    for (int it = 0; it < 8; it++) {
        int idx = t + 256 * it;          // 0..2047
        int r = idx >> 4;                // row 0..127
        int q = idx & 15;                // float4 col 0..15
        float4 v = __ldg(reinterpret_cast<const float4*>(
                             x + (size_t)(row0 + r) * DD) + q);
        uint32_t h0, l0, h1, l1;
        split2(v.x, v.y, h0, l0);
        split2(v.z, v.w, h1, l1);
        uint32_t off = (uint32_t)(r * 128 + q * 8);
        uint32_t so = off ^ ((off >> 3) & 0x70);
        sts_v2(sbase + AH_OFF + so, h0, h1);
        sts_v2(sbase + AL_OFF + so, l0, l1);
    }
    // ---- Load + split y tile -> Bh/Bl ----
#pragma unroll
    for (int it = 0; it < 8; it++) {
        int idx = t + 256 * it;
        int r = idx >> 4;
        int q = idx & 15;
        float4 v = __ldg(reinterpret_cast<const float4*>(
                             y + (size_t)(col0 + r) * DD) + q);
        uint32_t h0, l0, h1, l1;
        split2(v.x, v.y, h0, l0);
        split2(v.z, v.w, h1, l1);
        uint32_t off = (uint32_t)(r * 128 + q * 8);
        uint32_t so = off ^ ((off >> 3) & 0x70);
        sts_v2(sbase + BH_OFF + so, h0, h1);
        sts_v2(sbase + BL_OFF + so, l0, l1);
    }
    // ---- Norms into smem ----
    if (t < TILE) {
        xn_s[t] = g_xn[row0 + t];
        yn_s[t] = g_yn[col0 + t];
    }
    __syncthreads();

    // ---- Warp tiling ----
    const int warp_row = wid >> 2;          // 0..1 -> 64 rows
    const int warp_col = wid & 3;           // 0..3 -> 32 cols
    const int m_base = warp_row * 64;       // smem row base for A
    const int n_base = warp_col * 32;       // smem row base for B

    // ldmatrix lane address components
    const int a_row = m_base + (lane & 15);          // + 16*mtile
    const int a_half = lane >> 4;                    // k-chunk half
    const int b_row = n_base + ((lane >> 4) & 1) * 8 + (lane & 7);  // + 16*p
    const int b_half = (lane >> 3) & 1;

    float acc[4][4][4];
#pragma unroll
    for (int m = 0; m < 4; m++)
#pragma unroll
        for (int n = 0; n < 4; n++)
#pragma unroll
            for (int e = 0; e < 4; e++) acc[m][n][e] = 0.f;

#pragma unroll
    for (int kc = 0; kc < 4; kc++) {
        const int a_chunk = kc * 2 + a_half;
        const int b_chunk = kc * 2 + b_half;

        uint32_t ah[4][4];
#pragma unroll
        for (int m = 0; m < 4; m++)
            ldsm4(swz(sbase + AH_OFF, a_row + 16 * m, a_chunk),
                  ah[m][0], ah[m][1], ah[m][2], ah[m][3]);
        uint32_t bh[4][2];
#pragma unroll
        for (int p = 0; p < 2; p++)
            ldsm4(swz(sbase + BH_OFF, b_row + 16 * p, b_chunk),
                  bh[2 * p][0], bh[2 * p][1], bh[2 * p + 1][0], bh[2 * p + 1][1]);
#pragma unroll
        for (int m = 0; m < 4; m++)
#pragma unroll
            for (int n = 0; n < 4; n++)
                mma16816(acc[m][n][0], acc[m][n][1], acc[m][n][2], acc[m][n][3],
                         ah[m][0], ah[m][1], ah[m][2], ah[m][3],
                         bh[n][0], bh[n][1]);

        uint32_t bl[4][2];
#pragma unroll
        for (int p = 0; p < 2; p++)
            ldsm4(swz(sbase + BL_OFF, b_row + 16 * p, b_chunk),
                  bl[2 * p][0], bl[2 * p][1], bl[2 * p + 1][0], bl[2 * p + 1][1]);
#pragma unroll
        for (int m = 0; m < 4; m++)
#pragma unroll
            for (int n = 0; n < 4; n++)
                mma16816(acc[m][n][0], acc[m][n][1], acc[m][n][2], acc[m][n][3],
                         ah[m][0], ah[m][1], ah[m][2], ah[m][3],
                         bl[n][0], bl[n][1]);

        uint32_t al[4][4];
#pragma unroll
        for (int m = 0; m < 4; m++)
            ldsm4(swz(sbase + AL_OFF, a_row + 16 * m, a_chunk),
                  al[m][0], al[m][1], al[m][2], al[m][3]);
#pragma unroll
        for (int m = 0; m < 4; m++)
#pragma unroll
            for (int n = 0; n < 4; n++)
                mma16816(acc[m][n][0], acc[m][n][1], acc[m][n][2], acc[m][n][3],
                         al[m][0], al[m][1], al[m][2], al[m][3],
                         bh[n][0], bh[n][1]);
    }

    // ---- Epilogue: dist2 -> exp -> direct float2 stores ----
    const int group = lane >> 2;     // accum row within 16-tile
    const int tig   = lane & 3;      // accum col pair within 8-tile

    float xnv[4][2], ynv[4][2];
#pragma unroll
    for (int m = 0; m < 4; m++) {
        xnv[m][0] = xn_s[m_base + 16 * m + group];
        xnv[m][1] = xn_s[m_base + 16 * m + group + 8];
    }
#pragma unroll
    for (int n = 0; n < 4; n++) {
        ynv[n][0] = yn_s[n_base + 8 * n + 2 * tig];
        ynv[n][1] = yn_s[n_base + 8 * n + 2 * tig + 1];
    }

#pragma unroll
    for (int m = 0; m < 4; m++) {
        const size_t grow0 = (size_t)(row0 + m_base + 16 * m + group) * NN;
        const size_t grow1 = grow0 + (size_t)8 * NN;
#pragma unroll
        for (int n = 0; n < 4; n++) {
            const int gcol = col0 + n_base + 8 * n + 2 * tig;
            float e0 = __expf(fminf(fmaf(2.f, acc[m][n][0], -(xnv[m][0] + ynv[n][0])), 0.f));
            float e1 = __expf(fminf(fmaf(2.f, acc[m][n][1], -(xnv[m][0] + ynv[n][1])), 0.f));
            float e2 = __expf(fminf(fmaf(2.f, acc[m][n][2], -(xnv[m][1] + ynv[n][0])), 0.f));
            float e3 = __expf(fminf(fmaf(2.f, acc[m][n][3], -(xnv[m][1] + ynv[n][1])), 0.f));
            __stcs(reinterpret_cast<float2*>(out + grow0 + gcol), make_float2(e0, e1));
            __stcs(reinterpret_cast<float2*>(out + grow1 + gcol), make_float2(e2, e3));
        }
    }
}

// ---------------------------------------------------------------------------
extern "C" void kernel_launch(void* const* d_in, const int* in_sizes, int n_in,
                              void* d_out, int out_size) {
    const float* x = (const float*)d_in[0];
    const float* y = (const float*)d_in[1];
    float* out = (float*)d_out;
    (void)in_sizes; (void)n_in; (void)out_size;

    cudaFuncSetAttribute(rbf_mma_kernel,
                         cudaFuncAttributeMaxDynamicSharedMemorySize,
                         SMEM_DYN_BYTES);

    norms_kernel<<<NN / 256, 256>>>(x, y);
    dim3 grid(NN / TILE, NN / TILE);  // (64, 64)
    rbf_mma_kernel<<<grid, 256, SMEM_DYN_BYTES>>>(x, y, out);
}

// round 5
// speedup vs baseline: 2.2927x; 1.2296x over previous
#include <cuda_runtime.h>
#include <cuda_bf16.h>
#include <cstdint>

// RBF: out[i][j] = exp(-||x_i - y_j||^2), N=M=8192, D=64, fp32.
// dist2 = xn + yn - 2*dot. dot via bf16 hi/lo split on mma.sync (HMMA):
//   x = xh + xl (bf16 each); dot = xh.yh + xh.yl + xl.yh (xl.yl dropped).
// Round 5: inputs pre-split ONCE into bf16 hi/lo global arrays (layout matches
// smem tile rows exactly: 64 bf16 = 128 B), so the main kernel fills its
// swizzled smem tiles with bare 16B cp.async copies (no cvt, no registers).

#define NN 8192
#define DD 64
#define TILE 128

// smem byte offsets (dynamic): 4 arrays of 128 rows x 128B
#define AH_OFF 0
#define AL_OFF 16384
#define BH_OFF 32768
#define BL_OFF 49152
#define SMEM_DYN_BYTES 65536

__device__ float g_xn[NN];
__device__ float g_yn[NN];
__device__ __nv_bfloat16 g_xh[NN * DD];
__device__ __nv_bfloat16 g_xl[NN * DD];
__device__ __nv_bfloat16 g_yh[NN * DD];
__device__ __nv_bfloat16 g_yl[NN * DD];

// ------------------------- helpers -----------------------------------------
__device__ __forceinline__ uint32_t smem_u32(const void* p) {
    uint32_t a;
    asm("{ .reg .u64 t; cvta.to.shared.u64 t, %1; cvt.u32.u64 %0, t; }"
        : "=r"(a) : "l"(p));
    return a;
}

__device__ __forceinline__ void cp_async16(uint32_t saddr, const void* gaddr) {
    asm volatile("cp.async.cg.shared.global [%0], [%1], 16;"
                 :: "r"(saddr), "l"(gaddr) : "memory");
}

__device__ __forceinline__ void ldsm4(uint32_t addr, uint32_t& r0, uint32_t& r1,
                                      uint32_t& r2, uint32_t& r3) {
    asm volatile("ldmatrix.sync.aligned.m8n8.x4.shared.b16 {%0,%1,%2,%3}, [%4];"
                 : "=r"(r0), "=r"(r1), "=r"(r2), "=r"(r3) : "r"(addr));
}

__device__ __forceinline__ void mma16816(float& c0, float& c1, float& c2, float& c3,
                                         uint32_t a0, uint32_t a1, uint32_t a2,
                                         uint32_t a3, uint32_t b0, uint32_t b1) {
    asm volatile(
        "mma.sync.aligned.m16n8k16.row.col.f32.bf16.bf16.f32 "
        "{%0,%1,%2,%3}, {%4,%5,%6,%7}, {%8,%9}, {%0,%1,%2,%3};"
        : "+f"(c0), "+f"(c1), "+f"(c2), "+f"(c3)
        : "r"(a0), "r"(a1), "r"(a2), "r"(a3), "r"(b0), "r"(b1));
}

// swizzled address: row stride 128B, 16B chunk index XORed with row&7
__device__ __forceinline__ uint32_t swz(uint32_t base, int row, int chunk) {
    return base + row * 128 + (((unsigned)chunk ^ ((unsigned)row & 7u)) << 4);
}

// fp32 -> {hi,lo} bf16x2 packed pair for 2 consecutive values
__device__ __forceinline__ void split2(float v0, float v1,
                                       uint32_t& hp, uint32_t& lp) {
    __nv_bfloat16 h0 = __float2bfloat16(v0);
    __nv_bfloat16 h1 = __float2bfloat16(v1);
    __nv_bfloat16 l0 = __float2bfloat16(v0 - __bfloat162float(h0));
    __nv_bfloat16 l1 = __float2bfloat16(v1 - __bfloat162float(h1));
    __nv_bfloat162 hh(h0, h1), ll(l0, l1);
    hp = *reinterpret_cast<uint32_t*>(&hh);
    lp = *reinterpret_cast<uint32_t*>(&ll);
}

// ---------------------------------------------------------------------------
// Prepass: split x,y into bf16 hi/lo arrays + row norms.
// One thread per float4 chunk: tid>>4 = row, tid&15 = chunk. 16 lanes/row.
// ---------------------------------------------------------------------------
__global__ void presplit_kernel(const float* __restrict__ x,
                                const float* __restrict__ y) {
    int tid = blockIdx.x * blockDim.x + threadIdx.x;   // 0..131071
    int row = tid >> 4;
    int q = tid & 15;

    float4 vx = __ldg(reinterpret_cast<const float4*>(x + (size_t)row * DD) + q);
    float4 vy = __ldg(reinterpret_cast<const float4*>(y + (size_t)row * DD) + q);

    uint32_t h0, l0, h1, l1;
    split2(vx.x, vx.y, h0, l0);
    split2(vx.z, vx.w, h1, l1);
    *reinterpret_cast<uint2*>(&g_xh[(size_t)row * DD + q * 4]) = make_uint2(h0, h1);
    *reinterpret_cast<uint2*>(&g_xl[(size_t)row * DD + q * 4]) = make_uint2(l0, l1);
    split2(vy.x, vy.y, h0, l0);
    split2(vy.z, vy.w, h1, l1);
    *reinterpret_cast<uint2*>(&g_yh[(size_t)row * DD + q * 4]) = make_uint2(h0, h1);
    *reinterpret_cast<uint2*>(&g_yl[(size_t)row * DD + q * 4]) = make_uint2(l0, l1);

    float sx = vx.x * vx.x + vx.y * vx.y + vx.z * vx.z + vx.w * vx.w;
    float sy = vy.x * vy.x + vy.y * vy.y + vy.z * vy.z + vy.w * vy.w;
#pragma unroll
    for (int o = 8; o >= 1; o >>= 1) {
        sx += __shfl_xor_sync(0xffffffffu, sx, o, 16);
        sy += __shfl_xor_sync(0xffffffffu, sy, o, 16);
    }
    if (q == 0) {
        g_xn[row] = sx;
        g_yn[row] = sy;
    }
}

// ---------------------------------------------------------------------------
// Main kernel. 256 threads (8 warps: 2 row x 4 col), grid (64, 64).
// ---------------------------------------------------------------------------
__global__ __launch_bounds__(256, 2)
void rbf_mma_kernel(float* __restrict__ out) {
    extern __shared__ __align__(128) char smem_raw[];
    const uint32_t sbase = smem_u32(smem_raw);

    __shared__ float xn_s[TILE];
    __shared__ float yn_s[TILE];

    const int t    = threadIdx.x;
    const int wid  = t >> 5;
    const int lane = t & 31;
    const int row0 = blockIdx.y * TILE;
    const int col0 = blockIdx.x * TILE;

    // ---- Fill 4 smem tiles via cp.async: global row layout == smem row ----
    {
        const __nv_bfloat16* srcs[4] = {
            g_xh + (size_t)row0 * DD, g_xl + (size_t)row0 * DD,
            g_yh + (size_t)col0 * DD, g_yl + (size_t)col0 * DD};
        const uint32_t dsts[4] = {sbase + AH_OFF, sbase + AL_OFF,
                                  sbase + BH_OFF, sbase + BL_OFF};
#pragma unroll
        for (int a = 0; a < 4; a++) {
#pragma unroll
            for (int it = 0; it < 4; it++) {
                int idx = t + 256 * it;    // 0..1023
                int r = idx >> 3;          // row 0..127
                int q = idx & 7;           // 16B chunk 0..7
                cp_async16(swz(dsts[a], r, q),
                           srcs[a] + (size_t)r * DD + q * 8);
            }
        }
        asm volatile("cp.async.commit_group;" ::: "memory");
    }

    // ---- Norms into smem (regular loads, overlap with cp.async) ----
    if (t < TILE) {
        xn_s[t] = g_xn[row0 + t];
        yn_s[t] = g_yn[col0 + t];
    }

    asm volatile("cp.async.wait_group 0;" ::: "memory");
    __syncthreads();

    // ---- Warp tiling ----
    const int warp_row = wid >> 2;          // 0..1 -> 64 rows
    const int warp_col = wid & 3;           // 0..3 -> 32 cols
    const int m_base = warp_row * 64;
    const int n_base = warp_col * 32;

    const int a_row = m_base + (lane & 15);
    const int a_half = lane >> 4;
    const int b_row = n_base + ((lane >> 4) & 1) * 8 + (lane & 7);
    const int b_half = (lane >> 3) & 1;

    float acc[4][4][4];
#pragma unroll
    for (int m = 0; m < 4; m++)
#pragma unroll
        for (int n = 0; n < 4; n++)
#pragma unroll
            for (int e = 0; e < 4; e++) acc[m][n][e] = 0.f;

#pragma unroll
    for (int kc = 0; kc < 4; kc++) {
        const int a_chunk = kc * 2 + a_half;
        const int b_chunk = kc * 2 + b_half;

        uint32_t ah[4][4];
#pragma unroll
        for (int m = 0; m < 4; m++)
            ldsm4(swz(sbase + AH_OFF, a_row + 16 * m, a_chunk),
                  ah[m][0], ah[m][1], ah[m][2], ah[m][3]);
        uint32_t bh[4][2];
#pragma unroll
        for (int p = 0; p < 2; p++)
            ldsm4(swz(sbase + BH_OFF, b_row + 16 * p, b_chunk),
                  bh[2 * p][0], bh[2 * p][1], bh[2 * p + 1][0], bh[2 * p + 1][1]);
#pragma unroll
        for (int m = 0; m < 4; m++)
#pragma unroll
            for (int n = 0; n < 4; n++)
                mma16816(acc[m][n][0], acc[m][n][1], acc[m][n][2], acc[m][n][3],
                         ah[m][0], ah[m][1], ah[m][2], ah[m][3],
                         bh[n][0], bh[n][1]);

        uint32_t bl[4][2];
#pragma unroll
        for (int p = 0; p < 2; p++)
            ldsm4(swz(sbase + BL_OFF, b_row + 16 * p, b_chunk),
                  bl[2 * p][0], bl[2 * p][1], bl[2 * p + 1][0], bl[2 * p + 1][1]);
#pragma unroll
        for (int m = 0; m < 4; m++)
#pragma unroll
            for (int n = 0; n < 4; n++)
                mma16816(acc[m][n][0], acc[m][n][1], acc[m][n][2], acc[m][n][3],
                         ah[m][0], ah[m][1], ah[m][2], ah[m][3],
                         bl[n][0], bl[n][1]);

        uint32_t al[4][4];
#pragma unroll
        for (int m = 0; m < 4; m++)
            ldsm4(swz(sbase + AL_OFF, a_row + 16 * m, a_chunk),
                  al[m][0], al[m][1], al[m][2], al[m][3]);
#pragma unroll
        for (int m = 0; m < 4; m++)
#pragma unroll
            for (int n = 0; n < 4; n++)
                mma16816(acc[m][n][0], acc[m][n][1], acc[m][n][2], acc[m][n][3],
                         al[m][0], al[m][1], al[m][2], al[m][3],
                         bh[n][0], bh[n][1]);
    }

    // ---- Epilogue: dist2 -> exp -> direct float2 stores ----
    const int group = lane >> 2;
    const int tig   = lane & 3;

    float xnv[4][2], ynv[4][2];
#pragma unroll
    for (int m = 0; m < 4; m++) {
        xnv[m][0] = xn_s[m_base + 16 * m + group];
        xnv[m][1] = xn_s[m_base + 16 * m + group + 8];
    }
#pragma unroll
    for (int n = 0; n < 4; n++) {
        ynv[n][0] = yn_s[n_base + 8 * n + 2 * tig];
        ynv[n][1] = yn_s[n_base + 8 * n + 2 * tig + 1];
    }

#pragma unroll
    for (int m = 0; m < 4; m++) {
        const size_t grow0 = (size_t)(row0 + m_base + 16 * m + group) * NN;
        const size_t grow1 = grow0 + (size_t)8 * NN;
#pragma unroll
        for (int n = 0; n < 4; n++) {
            const int gcol = col0 + n_base + 8 * n + 2 * tig;
            float e0 = __expf(fminf(fmaf(2.f, acc[m][n][0], -(xnv[m][0] + ynv[n][0])), 0.f));
            float e1 = __expf(fminf(fmaf(2.f, acc[m][n][1], -(xnv[m][0] + ynv[n][1])), 0.f));
            float e2 = __expf(fminf(fmaf(2.f, acc[m][n][2], -(xnv[m][1] + ynv[n][0])), 0.f));
            float e3 = __expf(fminf(fmaf(2.f, acc[m][n][3], -(xnv[m][1] + ynv[n][1])), 0.f));
            __stcs(reinterpret_cast<float2*>(out + grow0 + gcol), make_float2(e0, e1));
            __stcs(reinterpret_cast<float2*>(out + grow1 + gcol), make_float2(e2, e3));
        }
    }
}

// ---------------------------------------------------------------------------
extern "C" void kernel_launch(void* const* d_in, const int* in_sizes, int n_in,
                              void* d_out, int out_size) {
    const float* x = (const float*)d_in[0];
    const float* y = (const float*)d_in[1];
    float* out = (float*)d_out;
    (void)in_sizes; (void)n_in; (void)out_size;

    cudaFuncSetAttribute(rbf_mma_kernel,
                         cudaFuncAttributeMaxDynamicSharedMemorySize,
                         SMEM_DYN_BYTES);

    presplit_kernel<<<(NN * DD / 4) / 256, 256>>>(x, y);
    dim3 grid(NN / TILE, NN / TILE);  // (64, 64)
    rbf_mma_kernel<<<grid, 256, SMEM_DYN_BYTES>>>(out);
}

// round 6
// speedup vs baseline: 2.3916x; 1.0431x over previous
#include <cuda_runtime.h>
#include <cuda_bf16.h>
#include <cstdint>

// RBF: out[i][j] = exp(-||x_i - y_j||^2), N=M=8192, D=64, fp32.
// dist2 = xn + yn - 2*dot; dot via bf16 hi/lo split on mma.sync (HMMA):
//   dot = xh.yh + xh.yl + xl.yh (xl.yl dropped; inputs pre-split to bf16).
// Round 6: persistent CTAs (2/SM), A-tile resident per row strip, B tile
// double-buffered with cp.async prefetch overlapping the MMA mainloop.

#define NN 8192
#define DD 64
#define TILE 128
#define NSM 148
#define NCTA (2 * NSM)          // 296
#define TOTTILES (64 * 64)      // 4096 output tiles

// smem layout (dynamic, from 128-aligned base):
//   A:  Ah @0, Al @16K                       (32 KB, resident per row strip)
//   B:  buf0 {Bh,Bl} @32K, buf1 {Bh,Bl} @64K (2 x 32 KB, double buffered)
#define AH_OFF 0
#define AL_OFF 16384
#define BH_OFF(buf) (32768 + (buf) * 32768)
#define BL_OFF(buf) (32768 + (buf) * 32768 + 16384)
#define SMEM_DYN_BYTES 98304

#define LOG2E      1.4426950408889634f
#define TWO_LOG2E  2.8853900817779268f

__device__ float g_xn[NN];   // ||x_i||^2 * log2(e)
__device__ float g_yn[NN];   // ||y_j||^2 * log2(e)
__device__ __nv_bfloat16 g_xh[NN * DD];
__device__ __nv_bfloat16 g_xl[NN * DD];
__device__ __nv_bfloat16 g_yh[NN * DD];
__device__ __nv_bfloat16 g_yl[NN * DD];

// ------------------------- helpers -----------------------------------------
__device__ __forceinline__ uint32_t smem_u32(const void* p) {
    uint32_t a;
    asm("{ .reg .u64 t; cvta.to.shared.u64 t, %1; cvt.u32.u64 %0, t; }"
        : "=r"(a) : "l"(p));
    return a;
}

__device__ __forceinline__ void cp_async16(uint32_t saddr, const void* gaddr) {
    asm volatile("cp.async.cg.shared.global [%0], [%1], 16;"
                 :: "r"(saddr), "l"(gaddr) : "memory");
}

__device__ __forceinline__ void cp_commit() {
    asm volatile("cp.async.commit_group;" ::: "memory");
}

__device__ __forceinline__ void cp_wait_all() {
    asm volatile("cp.async.wait_group 0;" ::: "memory");
}

__device__ __forceinline__ void ldsm4(uint32_t addr, uint32_t& r0, uint32_t& r1,
                                      uint32_t& r2, uint32_t& r3) {
    asm volatile("ldmatrix.sync.aligned.m8n8.x4.shared.b16 {%0,%1,%2,%3}, [%4];"
                 : "=r"(r0), "=r"(r1), "=r"(r2), "=r"(r3) : "r"(addr));
}

__device__ __forceinline__ void mma16816(float& c0, float& c1, float& c2, float& c3,
                                         uint32_t a0, uint32_t a1, uint32_t a2,
                                         uint32_t a3, uint32_t b0, uint32_t b1) {
    asm volatile(
        "mma.sync.aligned.m16n8k16.row.col.f32.bf16.bf16.f32 "
        "{%0,%1,%2,%3}, {%4,%5,%6,%7}, {%8,%9}, {%0,%1,%2,%3};"
        : "+f"(c0), "+f"(c1), "+f"(c2), "+f"(c3)
        : "r"(a0), "r"(a1), "r"(a2), "r"(a3), "r"(b0), "r"(b1));
}

__device__ __forceinline__ float ex2f(float v) {
    float r;
    asm("ex2.approx.ftz.f32 %0, %1;" : "=f"(r) : "f"(v));
    return r;
}

// swizzled address: row stride 128B, 16B chunk index XORed with row&7
__device__ __forceinline__ uint32_t swz(uint32_t base, int row, int chunk) {
    return base + row * 128 + (((unsigned)chunk ^ ((unsigned)row & 7u)) << 4);
}

// fp32 -> {hi,lo} bf16x2 packed pair for 2 consecutive values
__device__ __forceinline__ void split2(float v0, float v1,
                                       uint32_t& hp, uint32_t& lp) {
    __nv_bfloat16 h0 = __float2bfloat16(v0);
    __nv_bfloat16 h1 = __float2bfloat16(v1);
    __nv_bfloat16 l0 = __float2bfloat16(v0 - __bfloat162float(h0));
    __nv_bfloat16 l1 = __float2bfloat16(v1 - __bfloat162float(h1));
    __nv_bfloat162 hh(h0, h1), ll(l0, l1);
    hp = *reinterpret_cast<uint32_t*>(&hh);
    lp = *reinterpret_cast<uint32_t*>(&ll);
}

// ---------------------------------------------------------------------------
// Prepass: split x,y into bf16 hi/lo arrays + log2e-scaled row norms.
// ---------------------------------------------------------------------------
__global__ void presplit_kernel(const float* __restrict__ x,
                                const float* __restrict__ y) {
    int tid = blockIdx.x * blockDim.x + threadIdx.x;   // 0..131071
    int row = tid >> 4;
    int q = tid & 15;

    float4 vx = __ldg(reinterpret_cast<const float4*>(x + (size_t)row * DD) + q);
    float4 vy = __ldg(reinterpret_cast<const float4*>(y + (size_t)row * DD) + q);

    uint32_t h0, l0, h1, l1;
    split2(vx.x, vx.y, h0, l0);
    split2(vx.z, vx.w, h1, l1);
    *reinterpret_cast<uint2*>(&g_xh[(size_t)row * DD + q * 4]) = make_uint2(h0, h1);
    *reinterpret_cast<uint2*>(&g_xl[(size_t)row * DD + q * 4]) = make_uint2(l0, l1);
    split2(vy.x, vy.y, h0, l0);
    split2(vy.z, vy.w, h1, l1);
    *reinterpret_cast<uint2*>(&g_yh[(size_t)row * DD + q * 4]) = make_uint2(h0, h1);
    *reinterpret_cast<uint2*>(&g_yl[(size_t)row * DD + q * 4]) = make_uint2(l0, l1);

    float sx = vx.x * vx.x + vx.y * vx.y + vx.z * vx.z + vx.w * vx.w;
    float sy = vy.x * vy.x + vy.y * vy.y + vy.z * vy.z + vy.w * vy.w;
#pragma unroll
    for (int o = 8; o >= 1; o >>= 1) {
        sx += __shfl_xor_sync(0xffffffffu, sx, o, 16);
        sy += __shfl_xor_sync(0xffffffffu, sy, o, 16);
    }
    if (q == 0) {
        g_xn[row] = sx * LOG2E;
        g_yn[row] = sy * LOG2E;
    }
}

// ---------------------------------------------------------------------------
// tile fill helpers (all 256 threads; 16B cp.async into swizzled smem)
// ---------------------------------------------------------------------------
__device__ __forceinline__ void load_A(uint32_t sbase, int t, int row0) {
    const __nv_bfloat16* sh = g_xh + (size_t)row0 * DD;
    const __nv_bfloat16* sl = g_xl + (size_t)row0 * DD;
#pragma unroll
    for (int it = 0; it < 4; it++) {
        int idx = t + 256 * it;    // 0..1023
        int r = idx >> 3;
        int q = idx & 7;
        cp_async16(swz(sbase + AH_OFF, r, q), sh + (size_t)r * DD + q * 8);
        cp_async16(swz(sbase + AL_OFF, r, q), sl + (size_t)r * DD + q * 8);
    }
}

__device__ __forceinline__ void load_B(uint32_t sbase, int buf, int t, int col0) {
    const __nv_bfloat16* sh = g_yh + (size_t)col0 * DD;
    const __nv_bfloat16* sl = g_yl + (size_t)col0 * DD;
    const uint32_t bh = sbase + BH_OFF(buf);
    const uint32_t bl = sbase + BL_OFF(buf);
#pragma unroll
    for (int it = 0; it < 4; it++) {
        int idx = t + 256 * it;
        int r = idx >> 3;
        int q = idx & 7;
        cp_async16(swz(bh, r, q), sh + (size_t)r * DD + q * 8);
        cp_async16(swz(bl, r, q), sl + (size_t)r * DD + q * 8);
    }
}

// ---------------------------------------------------------------------------
// Main persistent kernel. 256 threads (8 warps: 2 row x 4 col), grid = 296.
// ---------------------------------------------------------------------------
__global__ __launch_bounds__(256, 2)
void rbf_mma_kernel(float* __restrict__ out) {
    extern __shared__ __align__(128) char smem_raw[];
    const uint32_t sbase = smem_u32(smem_raw);

    __shared__ float xn_s[TILE];
    __shared__ float yn_s[TILE];

    const int t    = threadIdx.x;
    const int wid  = t >> 5;
    const int lane = t & 31;
    const int b    = blockIdx.x;

    // static tile schedule: contiguous row-major runs
    const int base = TOTTILES / NCTA;            // 13
    const int rem  = TOTTILES % NCTA;            // 248
    const int cnt  = base + (b < rem);
    const int start = (b < rem) ? (base + 1) * b : rem * (base + 1) + base * (b - rem);

    // warp tiling constants
    const int warp_row = wid >> 2;
    const int warp_col = wid & 3;
    const int m_base = warp_row * 64;
    const int n_base = warp_col * 32;
    const int a_row = m_base + (lane & 15);
    const int a_half = lane >> 4;
    const int b_row = n_base + ((lane >> 4) & 1) * 8 + (lane & 7);
    const int b_half = (lane >> 3) & 1;
    const int group = lane >> 2;
    const int tig   = lane & 3;

    // ---- prologue: load A + B for first tile ----
    {
        int id0 = start;
        load_A(sbase, t, (id0 >> 6) * TILE);
        load_B(sbase, 0, t, (id0 & 63) * TILE);
        cp_commit();
        cp_wait_all();
        __syncthreads();
    }

    int buf = 0;
    for (int s = 0; s < cnt; s++) {
        const int id   = start + s;
        const int ti   = id >> 6;
        const int tj   = id & 63;
        const int row0 = ti * TILE;
        const int col0 = tj * TILE;

        // prefetch next B if it shares this row strip
        bool pf = false;
        if (s + 1 < cnt && ((id + 1) >> 6) == ti) {
            load_B(sbase, buf ^ 1, t, ((id + 1) & 63) * TILE);
            cp_commit();
            pf = true;
        }

        // norms for this tile (read after the post-mainloop barrier)
        if (t < TILE) {
            xn_s[t] = g_xn[row0 + t];
            yn_s[t] = g_yn[col0 + t];
        }

        // ---- mainloop ----
        const uint32_t bhb = sbase + BH_OFF(buf);
        const uint32_t blb = sbase + BL_OFF(buf);

        float acc[4][4][4];
#pragma unroll
        for (int m = 0; m < 4; m++)
#pragma unroll
            for (int n = 0; n < 4; n++)
#pragma unroll
                for (int e = 0; e < 4; e++) acc[m][n][e] = 0.f;

#pragma unroll
        for (int kc = 0; kc < 4; kc++) {
            const int a_chunk = kc * 2 + a_half;
            const int b_chunk = kc * 2 + b_half;

            uint32_t ah[4][4];
#pragma unroll
            for (int m = 0; m < 4; m++)
                ldsm4(swz(sbase + AH_OFF, a_row + 16 * m, a_chunk),
                      ah[m][0], ah[m][1], ah[m][2], ah[m][3]);
            uint32_t bh[4][2];
#pragma unroll
            for (int p = 0; p < 2; p++)
                ldsm4(swz(bhb, b_row + 16 * p, b_chunk),
                      bh[2 * p][0], bh[2 * p][1], bh[2 * p + 1][0], bh[2 * p + 1][1]);
#pragma unroll
            for (int m = 0; m < 4; m++)
#pragma unroll
                for (int n = 0; n < 4; n++)
                    mma16816(acc[m][n][0], acc[m][n][1], acc[m][n][2], acc[m][n][3],
                             ah[m][0], ah[m][1], ah[m][2], ah[m][3],
                             bh[n][0], bh[n][1]);

            uint32_t bl[4][2];
#pragma unroll
            for (int p = 0; p < 2; p++)
                ldsm4(swz(blb, b_row + 16 * p, b_chunk),
                      bl[2 * p][0], bl[2 * p][1], bl[2 * p + 1][0], bl[2 * p + 1][1]);
#pragma unroll
            for (int m = 0; m < 4; m++)
#pragma unroll
                for (int n = 0; n < 4; n++)
                    mma16816(acc[m][n][0], acc[m][n][1], acc[m][n][2], acc[m][n][3],
                             ah[m][0], ah[m][1], ah[m][2], ah[m][3],
                             bl[n][0], bl[n][1]);

            uint32_t al[4][4];
#pragma unroll
            for (int m = 0; m < 4; m++)
                ldsm4(swz(sbase + AL_OFF, a_row + 16 * m, a_chunk),
                      al[m][0], al[m][1], al[m][2], al[m][3]);
#pragma unroll
            for (int m = 0; m < 4; m++)
#pragma unroll
                for (int n = 0; n < 4; n++)
                    mma16816(acc[m][n][0], acc[m][n][1], acc[m][n][2], acc[m][n][3],
                             al[m][0], al[m][1], al[m][2], al[m][3],
                             bh[n][0], bh[n][1]);
        }

        __syncthreads();   // mainloop reads done; norms visible for epilogue

        // ---- epilogue: neg = min(2log2e*dot - (xn'+yn'), 0); out = 2^neg ----
        float xnv[4][2], ynv[4][2];
#pragma unroll
        for (int m = 0; m < 4; m++) {
            xnv[m][0] = xn_s[m_base + 16 * m + group];
            xnv[m][1] = xn_s[m_base + 16 * m + group + 8];
        }
#pragma unroll
        for (int n = 0; n < 4; n++) {
            ynv[n][0] = yn_s[n_base + 8 * n + 2 * tig];
            ynv[n][1] = yn_s[n_base + 8 * n + 2 * tig + 1];
        }

#pragma unroll
        for (int m = 0; m < 4; m++) {
            const size_t grow0 = (size_t)(row0 + m_base + 16 * m + group) * NN;
            const size_t grow1 = grow0 + (size_t)8 * NN;
#pragma unroll
            for (int n = 0; n < 4; n++) {
                const int gcol = col0 + n_base + 8 * n + 2 * tig;
                float e0 = ex2f(fminf(fmaf(TWO_LOG2E, acc[m][n][0], -(xnv[m][0] + ynv[n][0])), 0.f));
                float e1 = ex2f(fminf(fmaf(TWO_LOG2E, acc[m][n][1], -(xnv[m][0] + ynv[n][1])), 0.f));
                float e2 = ex2f(fminf(fmaf(TWO_LOG2E, acc[m][n][2], -(xnv[m][1] + ynv[n][0])), 0.f));
                float e3 = ex2f(fminf(fmaf(TWO_LOG2E, acc[m][n][3], -(xnv[m][1] + ynv[n][1])), 0.f));
                __stcs(reinterpret_cast<float2*>(out + grow0 + gcol), make_float2(e0, e1));
                __stcs(reinterpret_cast<float2*>(out + grow1 + gcol), make_float2(e2, e3));
            }
        }

        // ---- advance pipeline ----
        if (s + 1 < cnt) {
            if (pf) {
                cp_wait_all();
                __syncthreads();     // also orders epilogue reads before next norm writes
                buf ^= 1;
            } else {
                __syncthreads();     // all epilogue reads done
                const int nid = id + 1;
                load_A(sbase, t, (nid >> 6) * TILE);
                load_B(sbase, buf, t, (nid & 63) * TILE);
                cp_commit();
                cp_wait_all();
                __syncthreads();
            }
        }
    }
}

// ---------------------------------------------------------------------------
extern "C" void kernel_launch(void* const* d_in, const int* in_sizes, int n_in,
                              void* d_out, int out_size) {
    const float* x = (const float*)d_in[0];
    const float* y = (const float*)d_in[1];
    float* out = (float*)d_out;
    (void)in_sizes; (void)n_in; (void)out_size;

    cudaFuncSetAttribute(rbf_mma_kernel,
                         cudaFuncAttributeMaxDynamicSharedMemorySize,
                         SMEM_DYN_BYTES);

    presplit_kernel<<<(NN * DD / 4) / 256, 256>>>(x, y);
    rbf_mma_kernel<<<NCTA, 256, SMEM_DYN_BYTES>>>(out);
}

// round 7
// speedup vs baseline: 2.5004x; 1.0455x over previous
#include <cuda_runtime.h>
#include <cuda_bf16.h>
#include <cstdint>

// RBF: out[i][j] = exp(-||x_i - y_j||^2), N=M=8192, D=64, fp32.
// dist2 = xn + yn - 2*dot; dot via bf16 hi/lo split on mma.sync (HMMA).
// Round 7: barrier-free pipeline. __syncthreads removed from steady state;
// B-buffer readiness/reuse tracked by mbarriers (fill/read per buffer) so a
// warp's epilogue (MUFU+STG, no smem) overlaps other warps' MMA mainloops.

#define NN 8192
#define DD 64
#define TILE 128
#define NSM 148
#define NCTA (2 * NSM)          // 296
#define TOTTILES (64 * 64)      // 4096

// smem layout (dynamic): A resident, B double-buffered
#define AH_OFF 0
#define AL_OFF 16384
#define BH_OFF(buf) (32768 + (buf) * 32768)
#define BL_OFF(buf) (32768 + (buf) * 32768 + 16384)
#define SMEM_DYN_BYTES 98304

#define LOG2E      1.4426950408889634f
#define TWO_LOG2E  2.8853900817779268f

__device__ float g_xn[NN];   // ||x_i||^2 * log2(e)
__device__ float g_yn[NN];   // ||y_j||^2 * log2(e)
__device__ __nv_bfloat16 g_xh[NN * DD];
__device__ __nv_bfloat16 g_xl[NN * DD];
__device__ __nv_bfloat16 g_yh[NN * DD];
__device__ __nv_bfloat16 g_yl[NN * DD];

// ------------------------- helpers -----------------------------------------
__device__ __forceinline__ uint32_t smem_u32(const void* p) {
    uint32_t a;
    asm("{ .reg .u64 t; cvta.to.shared.u64 t, %1; cvt.u32.u64 %0, t; }"
        : "=r"(a) : "l"(p));
    return a;
}

__device__ __forceinline__ void cp_async16(uint32_t saddr, const void* gaddr) {
    asm volatile("cp.async.cg.shared.global [%0], [%1], 16;"
                 :: "r"(saddr), "l"(gaddr) : "memory");
}

__device__ __forceinline__ void mbar_init(uint32_t addr, uint32_t cnt) {
    asm volatile("mbarrier.init.shared.b64 [%0], %1;"
                 :: "r"(addr), "r"(cnt) : "memory");
}

// this thread arrives on mbar once all its prior cp.asyncs have completed
__device__ __forceinline__ void cp_arrive_noinc(uint32_t addr) {
    asm volatile("cp.async.mbarrier.arrive.noinc.shared.b64 [%0];"
                 :: "r"(addr) : "memory");
}

__device__ __forceinline__ void mbar_arrive(uint32_t addr) {
    asm volatile("{ .reg .b64 tk; mbarrier.arrive.shared.b64 tk, [%0]; }"
                 :: "r"(addr) : "memory");
}

__device__ __forceinline__ void mbar_wait(uint32_t addr, uint32_t parity) {
    asm volatile(
        "{\n\t.reg .pred P1;\n\t"
        "WL_%=:\n\t"
        "mbarrier.try_wait.parity.acquire.cta.shared::cta.b64 P1, [%0], %1, 0x989680;\n\t"
        "@P1 bra.uni WD_%=;\n\t"
        "bra.uni WL_%=;\n\t"
        "WD_%=:\n\t}"
        :: "r"(addr), "r"(parity) : "memory");
}

__device__ __forceinline__ void ldsm4(uint32_t addr, uint32_t& r0, uint32_t& r1,
                                      uint32_t& r2, uint32_t& r3) {
    asm volatile("ldmatrix.sync.aligned.m8n8.x4.shared.b16 {%0,%1,%2,%3}, [%4];"
                 : "=r"(r0), "=r"(r1), "=r"(r2), "=r"(r3) : "r"(addr));
}

__device__ __forceinline__ void mma16816(float& c0, float& c1, float& c2, float& c3,
                                         uint32_t a0, uint32_t a1, uint32_t a2,
                                         uint32_t a3, uint32_t b0, uint32_t b1) {
    asm volatile(
        "mma.sync.aligned.m16n8k16.row.col.f32.bf16.bf16.f32 "
        "{%0,%1,%2,%3}, {%4,%5,%6,%7}, {%8,%9}, {%0,%1,%2,%3};"
        : "+f"(c0), "+f"(c1), "+f"(c2), "+f"(c3)
        : "r"(a0), "r"(a1), "r"(a2), "r"(a3), "r"(b0), "r"(b1));
}

__device__ __forceinline__ float ex2f(float v) {
    float r;
    asm("ex2.approx.ftz.f32 %0, %1;" : "=f"(r) : "f"(v));
    return r;
}

__device__ __forceinline__ uint32_t swz(uint32_t base, int row, int chunk) {
    return base + row * 128 + (((unsigned)chunk ^ ((unsigned)row & 7u)) << 4);
}

__device__ __forceinline__ void split2(float v0, float v1,
                                       uint32_t& hp, uint32_t& lp) {
    __nv_bfloat16 h0 = __float2bfloat16(v0);
    __nv_bfloat16 h1 = __float2bfloat16(v1);
    __nv_bfloat16 l0 = __float2bfloat16(v0 - __bfloat162float(h0));
    __nv_bfloat16 l1 = __float2bfloat16(v1 - __bfloat162float(h1));
    __nv_bfloat162 hh(h0, h1), ll(l0, l1);
    hp = *reinterpret_cast<uint32_t*>(&hh);
    lp = *reinterpret_cast<uint32_t*>(&ll);
}

// ---------------------------------------------------------------------------
__global__ void presplit_kernel(const float* __restrict__ x,
                                const float* __restrict__ y) {
    int tid = blockIdx.x * blockDim.x + threadIdx.x;
    int row = tid >> 4;
    int q = tid & 15;

    float4 vx = __ldg(reinterpret_cast<const float4*>(x + (size_t)row * DD) + q);
    float4 vy = __ldg(reinterpret_cast<const float4*>(y + (size_t)row * DD) + q);

    uint32_t h0, l0, h1, l1;
    split2(vx.x, vx.y, h0, l0);
    split2(vx.z, vx.w, h1, l1);
    *reinterpret_cast<uint2*>(&g_xh[(size_t)row * DD + q * 4]) = make_uint2(h0, h1);
    *reinterpret_cast<uint2*>(&g_xl[(size_t)row * DD + q * 4]) = make_uint2(l0, l1);
    split2(vy.x, vy.y, h0, l0);
    split2(vy.z, vy.w, h1, l1);
    *reinterpret_cast<uint2*>(&g_yh[(size_t)row * DD + q * 4]) = make_uint2(h0, h1);
    *reinterpret_cast<uint2*>(&g_yl[(size_t)row * DD + q * 4]) = make_uint2(l0, l1);

    float sx = vx.x * vx.x + vx.y * vx.y + vx.z * vx.z + vx.w * vx.w;
    float sy = vy.x * vy.x + vy.y * vy.y + vy.z * vy.z + vy.w * vy.w;
#pragma unroll
    for (int o = 8; o >= 1; o >>= 1) {
        sx += __shfl_xor_sync(0xffffffffu, sx, o, 16);
        sy += __shfl_xor_sync(0xffffffffu, sy, o, 16);
    }
    if (q == 0) {
        g_xn[row] = sx * LOG2E;
        g_yn[row] = sy * LOG2E;
    }
}

// ---------------------------------------------------------------------------
__device__ __forceinline__ void load_A(uint32_t sbase, int t, int row0) {
    const __nv_bfloat16* sh = g_xh + (size_t)row0 * DD;
    const __nv_bfloat16* sl = g_xl + (size_t)row0 * DD;
#pragma unroll
    for (int it = 0; it < 4; it++) {
        int idx = t + 256 * it;
        int r = idx >> 3;
        int q = idx & 7;
        cp_async16(swz(sbase + AH_OFF, r, q), sh + (size_t)r * DD + q * 8);
        cp_async16(swz(sbase + AL_OFF, r, q), sl + (size_t)r * DD + q * 8);
    }
}

__device__ __forceinline__ void load_B(uint32_t sbase, int buf, int t, int col0) {
    const __nv_bfloat16* sh = g_yh + (size_t)col0 * DD;
    const __nv_bfloat16* sl = g_yl + (size_t)col0 * DD;
    const uint32_t bh = sbase + BH_OFF(buf);
    const uint32_t bl = sbase + BL_OFF(buf);
#pragma unroll
    for (int it = 0; it < 4; it++) {
        int idx = t + 256 * it;
        int r = idx >> 3;
        int q = idx & 7;
        cp_async16(swz(bh, r, q), sh + (size_t)r * DD + q * 8);
        cp_async16(swz(bl, r, q), sl + (size_t)r * DD + q * 8);
    }
}

// ---------------------------------------------------------------------------
// Persistent kernel, 256 threads (8 warps: 2x4), grid = 296 (2/SM).
// ---------------------------------------------------------------------------
__global__ __launch_bounds__(256, 2)
void rbf_mma_kernel(float* __restrict__ out) {
    extern __shared__ __align__(128) char smem_raw[];
    const uint32_t sbase = smem_u32(smem_raw);

    __shared__ __align__(8) uint64_t s_mbar[4];  // fill0, fill1, read0, read1

    const int t    = threadIdx.x;
    const int wid  = t >> 5;
    const int lane = t & 31;
    const int b    = blockIdx.x;

    const uint32_t fill_a0 = smem_u32(&s_mbar[0]);
    const uint32_t fill_a1 = smem_u32(&s_mbar[1]);
    const uint32_t read_a0 = smem_u32(&s_mbar[2]);
    const uint32_t read_a1 = smem_u32(&s_mbar[3]);

    if (t == 0) {
        mbar_init(fill_a0, 256);
        mbar_init(fill_a1, 256);
        mbar_init(read_a0, 256);
        mbar_init(read_a1, 256);
    }
    __syncthreads();

    // static tile schedule: contiguous row-major runs
    const int base  = TOTTILES / NCTA;
    const int rem   = TOTTILES % NCTA;
    const int cnt   = base + (b < rem);
    const int start = (b < rem) ? (base + 1) * b : rem * (base + 1) + base * (b - rem);

    // warp tiling constants
    const int warp_row = wid >> 2;
    const int warp_col = wid & 3;
    const int m_base = warp_row * 64;
    const int n_base = warp_col * 32;
    const int a_row = m_base + (lane & 15);
    const int a_half = lane >> 4;
    const int b_row = n_base + ((lane >> 4) & 1) * 8 + (lane & 7);
    const int b_half = (lane >> 3) & 1;
    const int group = lane >> 2;
    const int tig   = lane & 3;

    // prologue: A(row of first tile) + B(first tile) -> buf0, arm fill0
    load_A(sbase, t, (start >> 6) * TILE);
    load_B(sbase, 0, t, (start & 63) * TILE);
    cp_arrive_noinc(fill_a0);

    float xnv[4][2];   // persistent per row strip

    for (int s = 0; s < cnt; s++) {
        const int id   = start + s;
        const int ti   = id >> 6;
        const int tj   = id & 63;
        const int row0 = ti * TILE;
        const int col0 = tj * TILE;
        const int buf  = s & 1;
        const uint32_t fill_cur = buf ? fill_a1 : fill_a0;
        const uint32_t fill_nxt = buf ? fill_a0 : fill_a1;
        const uint32_t read_cur = buf ? read_a1 : read_a0;
        const uint32_t read_oth = buf ? read_a0 : read_a1;

        // 1. all warps done reading buf^1 (mainloop s-1)
        if (s > 0) mbar_wait(read_oth, ((s - 1) >> 1) & 1);

        const bool strip_entry = (s == 0) || (((id - 1) >> 6) != ti);

        // 2. deferred A+B load (row strip changed into this tile)
        if (s > 0 && strip_entry) {
            load_A(sbase, t, row0);
            load_B(sbase, buf, t, col0);
            cp_arrive_noinc(fill_cur);
        }
        // 3. prefetch next B if same row strip
        if (s + 1 < cnt && (((id + 1) >> 6) == ti)) {
            load_B(sbase, buf ^ 1, t, ((id + 1) & 63) * TILE);
            cp_arrive_noinc(fill_nxt);
        }

        // row-strip norms (persistent registers)
        if (strip_entry) {
#pragma unroll
            for (int m = 0; m < 4; m++) {
                xnv[m][0] = __ldg(&g_xn[row0 + m_base + 16 * m + group]);
                xnv[m][1] = __ldg(&g_xn[row0 + m_base + 16 * m + group + 8]);
            }
        }
        float ynv[4][2];
#pragma unroll
        for (int n = 0; n < 4; n++) {
            ynv[n][0] = __ldg(&g_yn[col0 + n_base + 8 * n + 2 * tig]);
            ynv[n][1] = __ldg(&g_yn[col0 + n_base + 8 * n + 2 * tig + 1]);
        }

        // 4. wait B(s) data ready
        mbar_wait(fill_cur, (s >> 1) & 1);

        // ---- mainloop ----
        const uint32_t bhb = sbase + BH_OFF(buf);
        const uint32_t blb = sbase + BL_OFF(buf);

        float acc[4][4][4];
#pragma unroll
        for (int m = 0; m < 4; m++)
#pragma unroll
            for (int n = 0; n < 4; n++)
#pragma unroll
                for (int e = 0; e < 4; e++) acc[m][n][e] = 0.f;

#pragma unroll
        for (int kc = 0; kc < 4; kc++) {
            const int a_chunk = kc * 2 + a_half;
            const int b_chunk = kc * 2 + b_half;

            uint32_t ah[4][4];
#pragma unroll
            for (int m = 0; m < 4; m++)
                ldsm4(swz(sbase + AH_OFF, a_row + 16 * m, a_chunk),
                      ah[m][0], ah[m][1], ah[m][2], ah[m][3]);
            uint32_t bh[4][2];
#pragma unroll
            for (int p = 0; p < 2; p++)
                ldsm4(swz(bhb, b_row + 16 * p, b_chunk),
                      bh[2 * p][0], bh[2 * p][1], bh[2 * p + 1][0], bh[2 * p + 1][1]);
#pragma unroll
            for (int m = 0; m < 4; m++)
#pragma unroll
                for (int n = 0; n < 4; n++)
                    mma16816(acc[m][n][0], acc[m][n][1], acc[m][n][2], acc[m][n][3],
                             ah[m][0], ah[m][1], ah[m][2], ah[m][3],
                             bh[n][0], bh[n][1]);

            uint32_t bl[4][2];
#pragma unroll
            for (int p = 0; p < 2; p++)
                ldsm4(swz(blb, b_row + 16 * p, b_chunk),
                      bl[2 * p][0], bl[2 * p][1], bl[2 * p + 1][0], bl[2 * p + 1][1]);
#pragma unroll
            for (int m = 0; m < 4; m++)
#pragma unroll
                for (int n = 0; n < 4; n++)
                    mma16816(acc[m][n][0], acc[m][n][1], acc[m][n][2], acc[m][n][3],
                             ah[m][0], ah[m][1], ah[m][2], ah[m][3],
                             bl[n][0], bl[n][1]);

            uint32_t al[4][4];
#pragma unroll
            for (int m = 0; m < 4; m++)
                ldsm4(swz(sbase + AL_OFF, a_row + 16 * m, a_chunk),
                      al[m][0], al[m][1], al[m][2], al[m][3]);
#pragma unroll
            for (int m = 0; m < 4; m++)
#pragma unroll
                for (int n = 0; n < 4; n++)
                    mma16816(acc[m][n][0], acc[m][n][1], acc[m][n][2], acc[m][n][3],
                             al[m][0], al[m][1], al[m][2], al[m][3],
                             bh[n][0], bh[n][1]);
        }

        // 5. this thread done reading smem tiles
        mbar_arrive(read_cur);

        // ---- epilogue (registers + global only; overlaps other warps' MMA) --
#pragma unroll
        for (int m = 0; m < 4; m++) {
            const size_t grow0 = (size_t)(row0 + m_base + 16 * m + group) * NN;
            const size_t grow1 = grow0 + (size_t)8 * NN;
#pragma unroll
            for (int n = 0; n < 4; n++) {
                const int gcol = col0 + n_base + 8 * n + 2 * tig;
                float e0 = ex2f(fminf(fmaf(TWO_LOG2E, acc[m][n][0], -(xnv[m][0] + ynv[n][0])), 0.f));
                float e1 = ex2f(fminf(fmaf(TWO_LOG2E, acc[m][n][1], -(xnv[m][0] + ynv[n][1])), 0.f));
                float e2 = ex2f(fminf(fmaf(TWO_LOG2E, acc[m][n][2], -(xnv[m][1] + ynv[n][0])), 0.f));
                float e3 = ex2f(fminf(fmaf(TWO_LOG2E, acc[m][n][3], -(xnv[m][1] + ynv[n][1])), 0.f));
                __stcs(reinterpret_cast<float2*>(out + grow0 + gcol), make_float2(e0, e1));
                __stcs(reinterpret_cast<float2*>(out + grow1 + gcol), make_float2(e2, e3));
            }
        }
    }
}

// ---------------------------------------------------------------------------
extern "C" void kernel_launch(void* const* d_in, const int* in_sizes, int n_in,
                              void* d_out, int out_size) {
    const float* x = (const float*)d_in[0];
    const float* y = (const float*)d_in[1];
    float* out = (float*)d_out;
    (void)in_sizes; (void)n_in; (void)out_size;

    cudaFuncSetAttribute(rbf_mma_kernel,
                         cudaFuncAttributeMaxDynamicSharedMemorySize,
                         SMEM_DYN_BYTES);

    presplit_kernel<<<(NN * DD / 4) / 256, 256>>>(x, y);
    rbf_mma_kernel<<<NCTA, 256, SMEM_DYN_BYTES>>>(out);
}